// round 1
// baseline (speedup 1.0000x reference)
#include <cuda_runtime.h>

#define N       8192
#define DIN     60
#define BM      128
#define BN      128
#define SPLIT   16
#define JCHUNK  (N / SPLIT)   // 512

// ---------------- scratch (no allocs allowed) ----------------
__device__ float g_z[N * 16];     // latent z [N,16]
__device__ float g_sq[N];         // ||z_i||^2
__device__ float g_acc[N * 61];   // [N][60 acc + 1 rowsum]

// ---------------- packed f32x2 helpers ----------------
static __device__ __forceinline__ unsigned long long pack2(float lo, float hi) {
    unsigned long long r;
    asm("mov.b64 %0, {%1, %2};" : "=l"(r) : "f"(lo), "f"(hi));
    return r;
}
static __device__ __forceinline__ void unpack2(unsigned long long v, float& lo, float& hi) {
    asm("mov.b64 {%0, %1}, %2;" : "=f"(lo), "=f"(hi) : "l"(v));
}
static __device__ __forceinline__ unsigned long long fma2(unsigned long long a,
                                                          unsigned long long b,
                                                          unsigned long long c) {
    unsigned long long d;
    asm("fma.rn.f32x2 %0, %1, %2, %3;" : "=l"(d) : "l"(a), "l"(b), "l"(c));
    return d;
}
static __device__ __forceinline__ unsigned long long mul2(unsigned long long a,
                                                          unsigned long long b) {
    unsigned long long d;
    asm("mul.rn.f32x2 %0, %1, %2;" : "=l"(d) : "l"(a), "l"(b));
    return d;
}

// ================= k1: z = fc2(fc1(x)), sq = ||z||^2, zero acc =================
__global__ __launch_bounds__(128) void k1_embed(
    const float* __restrict__ x,
    const float* __restrict__ w1, const float* __restrict__ b1,
    const float* __restrict__ w2, const float* __restrict__ b2)
{
    __shared__ float sw1[32 * 60], sb1[32], sw2[16 * 32], sb2[16];
    int tid = threadIdx.x;
    for (int idx = tid; idx < 32 * 60; idx += 128) sw1[idx] = w1[idx];
    for (int idx = tid; idx < 16 * 32; idx += 128) sw2[idx] = w2[idx];
    if (tid < 32) sb1[tid] = b1[tid];
    if (tid < 16) sb2[tid] = b2[tid];
    __syncthreads();

    int r = blockIdx.x * 128 + tid;

    float xr[60];
    const float4* xp = (const float4*)(x + r * 60);
#pragma unroll
    for (int k = 0; k < 15; k++) {
        float4 v = xp[k];
        xr[4 * k + 0] = v.x; xr[4 * k + 1] = v.y;
        xr[4 * k + 2] = v.z; xr[4 * k + 3] = v.w;
    }

    float h1[32];
#pragma unroll
    for (int o = 0; o < 32; o++) {
        float s = sb1[o];
#pragma unroll
        for (int k = 0; k < 60; k++) s = fmaf(sw1[o * 60 + k], xr[k], s);
        h1[o] = s;
    }

    float z[16];
    float sq = 0.f;
#pragma unroll
    for (int o = 0; o < 16; o++) {
        float s = sb2[o];
#pragma unroll
        for (int k = 0; k < 32; k++) s = fmaf(sw2[o * 32 + k], h1[k], s);
        z[o] = s;
        sq = fmaf(s, s, sq);
    }

    float4* zp = (float4*)(g_z + r * 16);
    zp[0] = make_float4(z[0], z[1], z[2], z[3]);
    zp[1] = make_float4(z[4], z[5], z[6], z[7]);
    zp[2] = make_float4(z[8], z[9], z[10], z[11]);
    zp[3] = make_float4(z[12], z[13], z[14], z[15]);
    g_sq[r] = sq;

    float* ap = g_acc + r * 61;
#pragma unroll
    for (int k = 0; k < 61; k++) ap[k] = 0.f;
}

// ================= k2: fused sigmoid-adjacency aggregation =================
// blockIdx.x: row tile (64), blockIdx.y: j-split (16). Thread owns one row i.
__global__ __launch_bounds__(128) void k2_aggregate(
    const float* __restrict__ x,
    const float* __restrict__ temp_p,
    const float* __restrict__ theta_p)
{
    __shared__ ulonglong2 s_x[BN * 15];  // x tile, float4 bits  (30 KB)
    __shared__ ulonglong2 s_z[BN * 4];   // z tile, float4 bits  (8 KB)
    __shared__ float      s_sq[BN];

    int tid = threadIdx.x;
    int i = blockIdx.x * BM + tid;
    float temp  = *temp_p;
    float theta = *theta_p;

    // z_i pre-scaled by -2 (distance = sq_i + sq_j + (-2 z_i)·z_j), packed
    unsigned long long zi[8];
    {
        const float4* zp = (const float4*)(g_z + i * 16);
#pragma unroll
        for (int q = 0; q < 4; q++) {
            float4 v = zp[q];
            zi[2 * q + 0] = pack2(-2.f * v.x, -2.f * v.y);
            zi[2 * q + 1] = pack2(-2.f * v.z, -2.f * v.w);
        }
    }
    float sqi = g_sq[i];

    unsigned long long acc[30];
#pragma unroll
    for (int k = 0; k < 30; k++) acc[k] = 0ull;
    float rowsum = 0.f;

    int jbase0 = blockIdx.y * JCHUNK;

    for (int t = 0; t < JCHUNK / BN; ++t) {
        int jbase = jbase0 + t * BN;
        __syncthreads();
        // cooperative tile load (layouts identical global<->shared)
        const float4* gx = (const float4*)(x + (size_t)jbase * 60);
#pragma unroll
        for (int q = 0; q < 15; q++) {
            int f = q * 128 + tid;
            float4 v = gx[f];
            s_x[f] = *(const ulonglong2*)&v;
        }
        const float4* gz = (const float4*)(g_z + (size_t)jbase * 16);
#pragma unroll
        for (int q = 0; q < 4; q++) {
            int f = q * 128 + tid;
            float4 v = gz[f];
            s_z[f] = *(const ulonglong2*)&v;
        }
        s_sq[tid] = g_sq[jbase + tid];
        __syncthreads();

#pragma unroll 2
        for (int jj = 0; jj < BN; ++jj) {
            // -2 * (z_i . z_j), two parallel packed chains
            ulonglong2 a = s_z[jj * 4 + 0];
            ulonglong2 b = s_z[jj * 4 + 1];
            ulonglong2 c = s_z[jj * 4 + 2];
            ulonglong2 d = s_z[jj * 4 + 3];
            unsigned long long p0 = mul2(zi[0], a.x);
            unsigned long long p1 = mul2(zi[1], a.y);
            p0 = fma2(zi[2], b.x, p0);
            p1 = fma2(zi[3], b.y, p1);
            p0 = fma2(zi[4], c.x, p0);
            p1 = fma2(zi[5], c.y, p1);
            p0 = fma2(zi[6], d.x, p0);
            p1 = fma2(zi[7], d.y, p1);
            float l0, h0, l1, h1;
            unpack2(p0, l0, h0);
            unpack2(p1, l1, h1);
            float dist = (sqi + s_sq[jj]) + ((l0 + h0) + (l1 + h1));
            dist = fmaxf(dist, 0.f);
            float arg = fmaf(-temp, dist, theta);
            float A = __fdividef(1.f, 1.f + __expf(-arg));
            if (jbase + jj == i) A = 1.f;   // diagonal forced to 1
            rowsum += A;
            unsigned long long A2 = pack2(A, A);
#pragma unroll
            for (int k = 0; k < 15; k++) {
                ulonglong2 v = s_x[jj * 15 + k];
                acc[2 * k + 0] = fma2(A2, v.x, acc[2 * k + 0]);
                acc[2 * k + 1] = fma2(A2, v.y, acc[2 * k + 1]);
            }
        }
    }

    // combine split partials
    float* dst = g_acc + (size_t)i * 61;
#pragma unroll
    for (int k = 0; k < 30; k++) {
        float lo, hi;
        unpack2(acc[k], lo, hi);
        atomicAdd(dst + 2 * k + 0, lo);
        atomicAdd(dst + 2 * k + 1, hi);
    }
    atomicAdd(dst + 60, rowsum);
}

// ================= k3: normalize -> fc3 -> fc6 -> softmax =================
__global__ __launch_bounds__(128) void k3_head(
    const float* __restrict__ w3, const float* __restrict__ b3,
    const float* __restrict__ w6, const float* __restrict__ b6,
    float* __restrict__ out)
{
    __shared__ float sw3[8 * 60], sb3[8], sw6[10 * 8], sb6[10];
    int tid = threadIdx.x;
    for (int idx = tid; idx < 480; idx += 128) sw3[idx] = w3[idx];
    if (tid < 8)  sb3[tid] = b3[tid];
    if (tid < 80) sw6[tid] = w6[tid];
    if (tid < 10) sb6[tid] = b6[tid];
    __syncthreads();

    int r = blockIdx.x * 128 + tid;
    const float* ap = g_acc + (size_t)r * 61;
    float inv = 1.f / ap[60];

    float h[60];
#pragma unroll
    for (int k = 0; k < 60; k++) h[k] = ap[k] * inv;

    float t[8];
#pragma unroll
    for (int o = 0; o < 8; o++) {
        float s = sb3[o];
#pragma unroll
        for (int k = 0; k < 60; k++) s = fmaf(sw3[o * 60 + k], h[k], s);
        t[o] = s;
    }

    float u[10];
    float m = -1e30f;
#pragma unroll
    for (int c = 0; c < 10; c++) {
        float s = sb6[c];
#pragma unroll
        for (int o = 0; o < 8; o++) s = fmaf(sw6[c * 8 + o], t[o], s);
        u[c] = s;
        m = fmaxf(m, s);
    }
    float denom = 0.f;
#pragma unroll
    for (int c = 0; c < 10; c++) { u[c] = __expf(u[c] - m); denom += u[c]; }
    float dinv = 1.f / denom;
#pragma unroll
    for (int c = 0; c < 10; c++) out[r * 10 + c] = u[c] * dinv;
}

// ================= launch =================
extern "C" void kernel_launch(void* const* d_in, const int* in_sizes, int n_in,
                              void* d_out, int out_size)
{
    const float* x     = (const float*)d_in[0];
    const float* w1    = (const float*)d_in[1];
    const float* b1    = (const float*)d_in[2];
    const float* w2    = (const float*)d_in[3];
    const float* b2    = (const float*)d_in[4];
    const float* w3    = (const float*)d_in[5];
    const float* b3    = (const float*)d_in[6];
    const float* w6    = (const float*)d_in[7];
    const float* b6    = (const float*)d_in[8];
    const float* temp  = (const float*)d_in[9];
    const float* theta = (const float*)d_in[10];
    float* out = (float*)d_out;

    k1_embed<<<N / 128, 128>>>(x, w1, b1, w2, b2);
    dim3 g2(N / BM, SPLIT);
    k2_aggregate<<<g2, 128>>>(x, temp, theta);
    k3_head<<<N / 128, 128>>>(w3, b3, w6, b6, out);
}

// round 3
// speedup vs baseline: 2.0950x; 2.0950x over previous
#include <cuda_runtime.h>
#include <cuda_fp16.h>
#include <cstdint>

#define N       8192
#define SPLIT   8
#define JCHUNK  (N / SPLIT)     // 1024
#define TILES   (JCHUNK / 128)  // 8
#define BROWSTRIDE 136          // sB row stride in halves (128 + 8 pad)

// ---------------- scratch (no allocs allowed) ----------------
__device__ float  g_z[N * 16];                 // latent z [N,16]
__device__ float  g_sq[N];                     // ||z_i||^2
__device__ __half g_xt[64 * N];                // x^T: rows 0..59 = x^T, row 60 = 1, 61..63 = 0
__device__ float  g_part[SPLIT * N * 64];      // [split][row][64] (60 h + rowsum@60 + pad)

// ---------------- packed f32x2 helpers ----------------
static __device__ __forceinline__ unsigned long long pack2(float lo, float hi) {
    unsigned long long r;
    asm("mov.b64 %0, {%1, %2};" : "=l"(r) : "f"(lo), "f"(hi));
    return r;
}
static __device__ __forceinline__ void unpack2(unsigned long long v, float& lo, float& hi) {
    asm("mov.b64 {%0, %1}, %2;" : "=f"(lo), "=f"(hi) : "l"(v));
}
static __device__ __forceinline__ unsigned long long fma2(unsigned long long a,
                                                          unsigned long long b,
                                                          unsigned long long c) {
    unsigned long long d;
    asm("fma.rn.f32x2 %0, %1, %2, %3;" : "=l"(d) : "l"(a), "l"(b), "l"(c));
    return d;
}
static __device__ __forceinline__ unsigned long long mul2(unsigned long long a,
                                                          unsigned long long b) {
    unsigned long long d;
    asm("mul.rn.f32x2 %0, %1, %2;" : "=l"(d) : "l"(a), "l"(b));
    return d;
}
static __device__ __forceinline__ unsigned long long add2(unsigned long long a,
                                                          unsigned long long b) {
    unsigned long long d;
    asm("add.rn.f32x2 %0, %1, %2;" : "=l"(d) : "l"(a), "l"(b));
    return d;
}
// pack two f32 -> f16x2 register: lo in bits[15:0], hi in bits[31:16]
static __device__ __forceinline__ uint32_t h2(float lo, float hi) {
    uint32_t r;
    asm("cvt.rn.f16x2.f32 %0, %1, %2;" : "=r"(r) : "f"(hi), "f"(lo));
    return r;
}
static __device__ __forceinline__ float ex2f(float x) {
    float r; asm("ex2.approx.f32 %0, %1;" : "=f"(r) : "f"(x)); return r;
}
static __device__ __forceinline__ float rcpf(float x) {
    float r; asm("rcp.approx.f32 %0, %1;" : "=f"(r) : "f"(x)); return r;
}
static __device__ __forceinline__ void mma16816(float c[4], uint32_t a0, uint32_t a1,
                                                uint32_t a2, uint32_t a3,
                                                uint32_t b0, uint32_t b1) {
    asm volatile(
        "mma.sync.aligned.m16n8k16.row.col.f32.f16.f16.f32 "
        "{%0,%1,%2,%3}, {%4,%5,%6,%7}, {%8,%9}, {%0,%1,%2,%3};"
        : "+f"(c[0]), "+f"(c[1]), "+f"(c[2]), "+f"(c[3])
        : "r"(a0), "r"(a1), "r"(a2), "r"(a3), "r"(b0), "r"(b1));
}

// ================= k1: z = fc2(fc1(x)), sq, x^T fp16 =================
__global__ __launch_bounds__(128) void k1_embed(
    const float* __restrict__ x,
    const float* __restrict__ w1, const float* __restrict__ b1,
    const float* __restrict__ w2, const float* __restrict__ b2)
{
    __shared__ float sw1[32 * 60], sb1[32], sw2[16 * 32], sb2[16];
    int tid = threadIdx.x;
    for (int idx = tid; idx < 32 * 60; idx += 128) sw1[idx] = w1[idx];
    for (int idx = tid; idx < 16 * 32; idx += 128) sw2[idx] = w2[idx];
    if (tid < 32) sb1[tid] = b1[tid];
    if (tid < 16) sb2[tid] = b2[tid];
    __syncthreads();

    int r = blockIdx.x * 128 + tid;

    float xr[60];
    const float4* xp = (const float4*)(x + (size_t)r * 60);
#pragma unroll
    for (int k = 0; k < 15; k++) {
        float4 v = xp[k];
        xr[4 * k + 0] = v.x; xr[4 * k + 1] = v.y;
        xr[4 * k + 2] = v.z; xr[4 * k + 3] = v.w;
    }

    // x^T fp16 (coalesced per-f across lanes)
#pragma unroll
    for (int f = 0; f < 60; f++) g_xt[(size_t)f * N + r] = __float2half(xr[f]);
    g_xt[(size_t)60 * N + r] = __float2half(1.0f);
    g_xt[(size_t)61 * N + r] = __float2half(0.0f);
    g_xt[(size_t)62 * N + r] = __float2half(0.0f);
    g_xt[(size_t)63 * N + r] = __float2half(0.0f);

    float h1[32];
#pragma unroll
    for (int o = 0; o < 32; o++) {
        float s = sb1[o];
#pragma unroll
        for (int k = 0; k < 60; k++) s = fmaf(sw1[o * 60 + k], xr[k], s);
        h1[o] = s;
    }

    float z[16];
    float sq = 0.f;
#pragma unroll
    for (int o = 0; o < 16; o++) {
        float s = sb2[o];
#pragma unroll
        for (int k = 0; k < 32; k++) s = fmaf(sw2[o * 32 + k], h1[k], s);
        z[o] = s;
        sq = fmaf(s, s, sq);
    }

    float4* zp = (float4*)(g_z + (size_t)r * 16);
    zp[0] = make_float4(z[0], z[1], z[2], z[3]);
    zp[1] = make_float4(z[4], z[5], z[6], z[7]);
    zp[2] = make_float4(z[8], z[9], z[10], z[11]);
    zp[3] = make_float4(z[12], z[13], z[14], z[15]);
    g_sq[r] = sq;
}

// ---------- k2 tile body ----------
// Computes A fragments for one 128-j tile (this warp's m16 rows), runs 8 K-step MMAs.
template <bool DIAG>
static __device__ __forceinline__ void tile_body(
    const __half* sB, const float* s_z, const float* s_sq,
    const unsigned long long zi0[8], const unsigned long long zi1[8],
    float sqi0, float sqi1, float tmL, float thL,
    int g, int t, int dl0, float C[8][4])
{
#pragma unroll
    for (int ks = 0; ks < 8; ks++) {
        float Af0[4], Af1[4];
#pragma unroll
        for (int cu = 0; cu < 4; cu++) {
            int jl = ks * 16 + ((cu >> 1) << 3) + 2 * t + (cu & 1);
            const float* zp = s_z + jl * 20;
            unsigned long long za0 = *(const unsigned long long*)(zp + 0);
            unsigned long long za1 = *(const unsigned long long*)(zp + 2);
            unsigned long long zb0 = *(const unsigned long long*)(zp + 4);
            unsigned long long zb1 = *(const unsigned long long*)(zp + 6);
            unsigned long long zc0 = *(const unsigned long long*)(zp + 8);
            unsigned long long zc1 = *(const unsigned long long*)(zp + 10);
            unsigned long long zd0 = *(const unsigned long long*)(zp + 12);
            unsigned long long zd1 = *(const unsigned long long*)(zp + 14);
            float sqj = s_sq[jl];

            // row0 dot (-2 z_i . z_j), two chains
            unsigned long long p0 = mul2(zi0[0], za0);
            unsigned long long p1 = mul2(zi0[1], za1);
            p0 = fma2(zi0[2], zb0, p0);  p1 = fma2(zi0[3], zb1, p1);
            p0 = fma2(zi0[4], zc0, p0);  p1 = fma2(zi0[5], zc1, p1);
            p0 = fma2(zi0[6], zd0, p0);  p1 = fma2(zi0[7], zd1, p1);
            // row1 dot
            unsigned long long q0 = mul2(zi1[0], za0);
            unsigned long long q1 = mul2(zi1[1], za1);
            q0 = fma2(zi1[2], zb0, q0);  q1 = fma2(zi1[3], zb1, q1);
            q0 = fma2(zi1[4], zc0, q0);  q1 = fma2(zi1[5], zc1, q1);
            q0 = fma2(zi1[6], zd0, q0);  q1 = fma2(zi1[7], zd1, q1);

            unsigned long long ps = add2(p0, p1);
            unsigned long long qs = add2(q0, q1);
            float pl, ph, ql, qh;
            unpack2(ps, pl, ph);
            unpack2(qs, ql, qh);

            float d0 = fmaxf((sqi0 + sqj) + (pl + ph), 0.f);
            float d1 = fmaxf((sqi1 + sqj) + (ql + qh), 0.f);
            // A = sigmoid(theta - temp*d) = 1/(1 + 2^( (temp*d - theta)*log2e ))
            float e0 = ex2f(fmaf(tmL, d0, thL));
            float e1 = ex2f(fmaf(tmL, d1, thL));
            float A0 = rcpf(1.f + e0);
            float A1 = rcpf(1.f + e1);
            if (DIAG) {
                if (jl == dl0)     A0 = 1.f;
                if (jl == dl0 + 8) A1 = 1.f;
            }
            Af0[cu] = A0;
            Af1[cu] = A1;
        }
        uint32_t a0 = h2(Af0[0], Af0[1]);
        uint32_t a1 = h2(Af1[0], Af1[1]);
        uint32_t a2 = h2(Af0[2], Af0[3]);
        uint32_t a3 = h2(Af1[2], Af1[3]);

#pragma unroll
        for (int nt = 0; nt < 8; nt++) {
            const __half* bp = sB + (nt * 8 + g) * BROWSTRIDE + ks * 16 + 2 * t;
            uint32_t b0 = *(const uint32_t*)(bp);
            uint32_t b1 = *(const uint32_t*)(bp + 8);
            mma16816(C[nt], a0, a1, a2, a3, b0, b1);
        }
    }
}

// ================= k2: fused sigmoid-adjacency + HMMA PV =================
// grid (64 i-tiles, SPLIT). 128 threads = 4 warps; warp handles 16 rows per mt pass.
__global__ __launch_bounds__(128) void k2_aggregate(
    const float* __restrict__ temp_p,
    const float* __restrict__ theta_p)
{
    __shared__ __align__(16) __half sB[64 * BROWSTRIDE];   // x^T tile [64 n][128 k], padded
    __shared__ __align__(16) float  s_z[128 * 20];         // z tile, padded rows
    __shared__ float s_sq[128];

    const int tid = threadIdx.x;
    const int wid = tid >> 5;
    const int lane = tid & 31;
    const int g = lane >> 2;
    const int t = lane & 3;

    const int rowBase = blockIdx.x * 128;
    const int jbase0  = blockIdx.y * JCHUNK;

    const float temp  = *temp_p;
    const float theta = *theta_p;
    const float L2E = 1.4426950408889634f;
    const float tmL = temp * L2E;
    const float thL = -theta * L2E;

#pragma unroll
    for (int mt = 0; mt < 2; mt++) {
        const int rl0 = wid * 32 + mt * 16 + g;     // block-local row of fragment row0
        const int rg0 = rowBase + rl0;

        // z_i rows (x -2), packed f32x2
        unsigned long long zi0[8], zi1[8];
        {
            const float4* z0p = (const float4*)(g_z + (size_t)rg0 * 16);
            const float4* z1p = (const float4*)(g_z + (size_t)(rg0 + 8) * 16);
#pragma unroll
            for (int q = 0; q < 4; q++) {
                float4 v = z0p[q];
                zi0[2 * q + 0] = pack2(-2.f * v.x, -2.f * v.y);
                zi0[2 * q + 1] = pack2(-2.f * v.z, -2.f * v.w);
                float4 w = z1p[q];
                zi1[2 * q + 0] = pack2(-2.f * w.x, -2.f * w.y);
                zi1[2 * q + 1] = pack2(-2.f * w.z, -2.f * w.w);
            }
        }
        const float sqi0 = g_sq[rg0];
        const float sqi1 = g_sq[rg0 + 8];

        float C[8][4];
#pragma unroll
        for (int nt = 0; nt < 8; nt++)
#pragma unroll
            for (int c = 0; c < 4; c++) C[nt][c] = 0.f;

        for (int tl = 0; tl < TILES; ++tl) {
            const int jbase = jbase0 + tl * 128;
            __syncthreads();
            // --- cooperative loads ---
#pragma unroll
            for (int q = 0; q < 8; q++) {         // B tile: 64 rows x 128 halves
                int e = q * 128 + tid;
                int rr = e >> 4, gg = e & 15;
                const uint4* src = (const uint4*)(g_xt + (size_t)rr * N + jbase + gg * 8);
                *(uint4*)(sB + rr * BROWSTRIDE + gg * 8) = *src;
            }
#pragma unroll
            for (int q = 0; q < 4; q++) {         // z tile: 128 rows x 16 floats
                int e = q * 128 + tid;
                int row = e >> 2, qq = e & 3;
                const float4* src = (const float4*)(g_z + (size_t)(jbase + row) * 16 + qq * 4);
                *(float4*)(s_z + row * 20 + qq * 4) = *src;
            }
            s_sq[tid] = g_sq[jbase + tid];
            __syncthreads();

            if (jbase == rowBase)
                tile_body<true >(sB, s_z, s_sq, zi0, zi1, sqi0, sqi1, tmL, thL, g, t, rl0, C);
            else
                tile_body<false>(sB, s_z, s_sq, zi0, zi1, sqi0, sqi1, tmL, thL, g, t, rl0, C);
        }

        // --- store partials: [split][row][64] ---
        float* base0 = g_part + ((size_t)blockIdx.y * N + rg0) * 64;
        float* base1 = base0 + (size_t)8 * 64;   // row rg0+8
#pragma unroll
        for (int nt = 0; nt < 8; nt++) {
            int col = nt * 8 + 2 * t;
            *(float2*)(base0 + col) = make_float2(C[nt][0], C[nt][1]);
            *(float2*)(base1 + col) = make_float2(C[nt][2], C[nt][3]);
        }
    }
}

// ================= k3: reduce splits -> normalize -> fc3 -> fc6 -> softmax =================
__global__ __launch_bounds__(128) void k3_head(
    const float* __restrict__ w3, const float* __restrict__ b3,
    const float* __restrict__ w6, const float* __restrict__ b6,
    float* __restrict__ out)
{
    __shared__ float sw3[8 * 60], sb3[8], sw6[10 * 8], sb6[10];
    int tid = threadIdx.x;
    for (int idx = tid; idx < 480; idx += 128) sw3[idx] = w3[idx];
    if (tid < 8)  sb3[tid] = b3[tid];
    if (tid < 80) sw6[tid] = w6[tid];
    if (tid < 10) sb6[tid] = b6[tid];
    __syncthreads();

    int r = blockIdx.x * 128 + tid;

    float h[64];
#pragma unroll
    for (int c = 0; c < 64; c++) h[c] = 0.f;
#pragma unroll
    for (int s = 0; s < SPLIT; s++) {
        const float4* p = (const float4*)(g_part + ((size_t)s * N + r) * 64);
#pragma unroll
        for (int q = 0; q < 16; q++) {
            float4 v = p[q];
            h[4 * q + 0] += v.x; h[4 * q + 1] += v.y;
            h[4 * q + 2] += v.z; h[4 * q + 3] += v.w;
        }
    }
    float inv = 1.f / h[60];
#pragma unroll
    for (int c = 0; c < 60; c++) h[c] *= inv;

    float tv[8];
#pragma unroll
    for (int o = 0; o < 8; o++) {
        float s = sb3[o];
#pragma unroll
        for (int k = 0; k < 60; k++) s = fmaf(sw3[o * 60 + k], h[k], s);
        tv[o] = s;
    }

    float u[10];
    float m = -1e30f;
#pragma unroll
    for (int c = 0; c < 10; c++) {
        float s = sb6[c];
#pragma unroll
        for (int o = 0; o < 8; o++) s = fmaf(sw6[c * 8 + o], tv[o], s);
        u[c] = s;
        m = fmaxf(m, s);
    }
    float denom = 0.f;
#pragma unroll
    for (int c = 0; c < 10; c++) { u[c] = __expf(u[c] - m); denom += u[c]; }
    float dinv = 1.f / denom;
#pragma unroll
    for (int c = 0; c < 10; c++) out[r * 10 + c] = u[c] * dinv;
}

// ================= launch =================
extern "C" void kernel_launch(void* const* d_in, const int* in_sizes, int n_in,
                              void* d_out, int out_size)
{
    const float* x     = (const float*)d_in[0];
    const float* w1    = (const float*)d_in[1];
    const float* b1    = (const float*)d_in[2];
    const float* w2    = (const float*)d_in[3];
    const float* b2    = (const float*)d_in[4];
    const float* w3    = (const float*)d_in[5];
    const float* b3    = (const float*)d_in[6];
    const float* w6    = (const float*)d_in[7];
    const float* b6    = (const float*)d_in[8];
    const float* temp  = (const float*)d_in[9];
    const float* theta = (const float*)d_in[10];
    float* out = (float*)d_out;

    k1_embed<<<N / 128, 128>>>(x, w1, b1, w2, b2);
    dim3 g2(N / 128, SPLIT);
    k2_aggregate<<<g2, 128>>>(temp, theta);
    k3_head<<<N / 128, 128>>>(w3, b3, w6, b6, out);
}

// round 4
// speedup vs baseline: 3.7259x; 1.7784x over previous
#include <cuda_runtime.h>
#include <cuda_fp16.h>
#include <cstdint>

#define N       8192
#define SPLIT   8
#define JCHUNK  (N / SPLIT)     // 1024
#define TILES   (JCHUNK / 128)  // 8
#define XSTRIDE 72              // sB row stride (halves): 64 + 8 pad
#define ZSTRIDE 24              // z tile row stride (halves): 16 + 8 pad

// ---------------- scratch (no allocs allowed) ----------------
__device__ __half g_x16[N * 64];        // [r][0..59]=x, [60]=1, [61..63]=0
__device__ __half g_zh[N * 16];         // z hi (fp16)
__device__ __half g_zl[N * 16];         // z lo (fp16 residual)
__device__ float  g_tq[N];              // temp*log2e*||z||^2
__device__ float  g_part[SPLIT * N * 64];

// ---------------- helpers ----------------
static __device__ __forceinline__ uint32_t smem_u32(const void* p) {
    uint32_t a;
    asm("{ .reg .u64 t; cvta.to.shared.u64 t, %1; cvt.u32.u64 %0, t; }" : "=r"(a) : "l"(p));
    return a;
}
static __device__ __forceinline__ uint32_t h2(float lo, float hi) {
    uint32_t r;
    asm("cvt.rn.f16x2.f32 %0, %1, %2;" : "=r"(r) : "f"(hi), "f"(lo));
    return r;
}
static __device__ __forceinline__ float ex2f(float x) {
    float r; asm("ex2.approx.f32 %0, %1;" : "=f"(r) : "f"(x)); return r;
}
static __device__ __forceinline__ float rcpf(float x) {
    float r; asm("rcp.approx.f32 %0, %1;" : "=f"(r) : "f"(x)); return r;
}
static __device__ __forceinline__ void mma16816(float c[4], const uint32_t a[4],
                                                uint32_t b0, uint32_t b1) {
    asm volatile(
        "mma.sync.aligned.m16n8k16.row.col.f32.f16.f16.f32 "
        "{%0,%1,%2,%3}, {%4,%5,%6,%7}, {%8,%9}, {%0,%1,%2,%3};"
        : "+f"(c[0]), "+f"(c[1]), "+f"(c[2]), "+f"(c[3])
        : "r"(a[0]), "r"(a[1]), "r"(a[2]), "r"(a[3]), "r"(b0), "r"(b1));
}
static __device__ __forceinline__ void ldsm_x2(uint32_t r[2], uint32_t addr) {
    asm volatile("ldmatrix.sync.aligned.m8n8.x2.shared.b16 {%0,%1}, [%2];"
                 : "=r"(r[0]), "=r"(r[1]) : "r"(addr));
}
static __device__ __forceinline__ void ldsm_x4_t(uint32_t r[4], uint32_t addr) {
    asm volatile("ldmatrix.sync.aligned.m8n8.x4.trans.shared.b16 {%0,%1,%2,%3}, [%4];"
                 : "=r"(r[0]), "=r"(r[1]), "=r"(r[2]), "=r"(r[3]) : "r"(addr));
}
static __device__ __forceinline__ uint32_t ld32g(const __half* p) {
    return *reinterpret_cast<const uint32_t*>(p);
}

// ================= k1: fold fc2(fc1(x)) into one 16x60 GEMV, split z, x fp16 =================
// 2 threads per row. grid 128 x 128 threads.
__global__ __launch_bounds__(128) void k1_embed(
    const float* __restrict__ x,
    const float* __restrict__ w1, const float* __restrict__ b1,
    const float* __restrict__ w2, const float* __restrict__ b2,
    const float* __restrict__ temp_p)
{
    __shared__ float sw1[32 * 60], sw2[16 * 32], sb1[32], sb2[16];
    __shared__ float sW[16 * 60], sb21[16];
    int tid = threadIdx.x;
    for (int i = tid; i < 32 * 60; i += 128) sw1[i] = w1[i];
    for (int i = tid; i < 16 * 32; i += 128) sw2[i] = w2[i];
    if (tid < 32) sb1[tid] = b1[tid];
    if (tid < 16) sb2[tid] = b2[tid];
    __syncthreads();

    // W21 = W2 @ W1  (16x60), b21 = W2 @ b1 + b2
    for (int e = tid; e < 960; e += 128) {
        int o = e / 60, k = e % 60;
        float s = 0.f;
#pragma unroll
        for (int m = 0; m < 32; m++) s = fmaf(sw2[o * 32 + m], sw1[m * 60 + k], s);
        sW[e] = s;
    }
    if (tid < 16) {
        float s = sb2[tid];
#pragma unroll
        for (int m = 0; m < 32; m++) s = fmaf(sw2[tid * 32 + m], sb1[m], s);
        sb21[tid] = s;
    }
    __syncthreads();

    int gt = blockIdx.x * 128 + tid;
    int r = gt >> 1;
    int half = gt & 1;

    float xr[60];
    const float4* xp = (const float4*)(x + (size_t)r * 60);
#pragma unroll
    for (int k = 0; k < 15; k++) {
        float4 v = xp[k];
        xr[4 * k + 0] = v.x; xr[4 * k + 1] = v.y;
        xr[4 * k + 2] = v.z; xr[4 * k + 3] = v.w;
    }

    // this thread's 8 z outputs
    float z[8];
    float sqp = 0.f;
#pragma unroll
    for (int oo = 0; oo < 8; oo++) {
        int o = half * 8 + oo;
        float s = sb21[o];
#pragma unroll
        for (int k = 0; k < 60; k++) s = fmaf(sW[o * 60 + k], xr[k], s);
        z[oo] = s;
        sqp = fmaf(s, s, sqp);
    }
    float sq = sqp + __shfl_xor_sync(0xffffffffu, sqp, 1);
    if (half == 0) g_tq[r] = (*temp_p) * 1.4426950408889634f * sq;

    // z split hi/lo
    union { __half h[8]; uint4 v; } zh, zl;
#pragma unroll
    for (int oo = 0; oo < 8; oo++) {
        __half hi = __float2half_rn(z[oo]);
        zh.h[oo] = hi;
        zl.h[oo] = __float2half_rn(z[oo] - __half2float(hi));
    }
    *reinterpret_cast<uint4*>(g_zh + (size_t)r * 16 + half * 8) = zh.v;
    *reinterpret_cast<uint4*>(g_zl + (size_t)r * 16 + half * 8) = zl.v;

    // x16 row: half0 -> f 0..31, half1 -> f 32..63 (60=1, 61..63=0)
    union { __half h[32]; uint4 v[4]; } xo;
    if (half == 0) {
#pragma unroll
        for (int f = 0; f < 32; f++) xo.h[f] = __float2half_rn(xr[f]);
    } else {
#pragma unroll
        for (int f = 0; f < 28; f++) xo.h[f] = __float2half_rn(xr[32 + f]);
        xo.h[28] = __float2half_rn(1.0f);
        xo.h[29] = __float2half_rn(0.0f);
        xo.h[30] = __float2half_rn(0.0f);
        xo.h[31] = __float2half_rn(0.0f);
    }
    uint4* xd = reinterpret_cast<uint4*>(g_x16 + (size_t)r * 64 + half * 32);
#pragma unroll
    for (int q = 0; q < 4; q++) xd[q] = xo.v[q];
}

// ---------------- k2 per-tile body ----------------
template <bool DIAG>
static __device__ __forceinline__ void k2_tile(
    uint32_t pvBase, uint32_t zhBase, uint32_t zlBase, const float* stq,
    const uint32_t aih[2][4], const uint32_t ail[2][4], const float cr[2][2],
    float mS, int wid, int g, int t, float C[2][8][4])
{
#pragma unroll
    for (int ks = 0; ks < 8; ks++) {
        float2 tqa = *(const float2*)(stq + ks * 16 + 2 * t);
        float2 tqb = *(const float2*)(stq + ks * 16 + 8 + 2 * t);
        uint32_t zh0[2], zl0[2], zh1[2], zl1[2];
        ldsm_x2(zh0, zhBase + (ks * 16 + 0) * (ZSTRIDE * 2));
        ldsm_x2(zl0, zlBase + (ks * 16 + 0) * (ZSTRIDE * 2));
        ldsm_x2(zh1, zhBase + (ks * 16 + 8) * (ZSTRIDE * 2));
        ldsm_x2(zl1, zlBase + (ks * 16 + 8) * (ZSTRIDE * 2));
#pragma unroll
        for (int rg = 0; rg < 2; rg++) {
            float S0[4] = {0.f, 0.f, 0.f, 0.f};
            float S1[4] = {0.f, 0.f, 0.f, 0.f};
            mma16816(S0, aih[rg], zh0[0], zh0[1]);   // hi*hi
            mma16816(S0, ail[rg], zh0[0], zh0[1]);   // lo*hi
            mma16816(S0, aih[rg], zl0[0], zl0[1]);   // hi*lo
            mma16816(S1, aih[rg], zh1[0], zh1[1]);
            mma16816(S1, ail[rg], zh1[0], zh1[1]);
            mma16816(S1, aih[rg], zl1[0], zl1[1]);

            float ccA0 = cr[rg][0] + tqa.x, ccA1 = cr[rg][0] + tqa.y;
            float ccB0 = cr[rg][1] + tqa.x, ccB1 = cr[rg][1] + tqa.y;
            float ccC0 = cr[rg][0] + tqb.x, ccC1 = cr[rg][0] + tqb.y;
            float ccD0 = cr[rg][1] + tqb.x, ccD1 = cr[rg][1] + tqb.y;

            float A00 = rcpf(1.f + ex2f(fmaf(mS, S0[0], ccA0)));
            float A01 = rcpf(1.f + ex2f(fmaf(mS, S0[1], ccA1)));
            float A10 = rcpf(1.f + ex2f(fmaf(mS, S0[2], ccB0)));
            float A11 = rcpf(1.f + ex2f(fmaf(mS, S0[3], ccB1)));
            float B00 = rcpf(1.f + ex2f(fmaf(mS, S1[0], ccC0)));
            float B01 = rcpf(1.f + ex2f(fmaf(mS, S1[1], ccC1)));
            float B10 = rcpf(1.f + ex2f(fmaf(mS, S1[2], ccD0)));
            float B11 = rcpf(1.f + ex2f(fmaf(mS, S1[3], ccD1)));

            if (DIAG) {
                int rAl = wid * 32 + rg * 16 + g;
                int rBl = rAl + 8;
                int c0 = ks * 16 + 2 * t;
                if (c0     == rAl) A00 = 1.f;
                if (c0 + 1 == rAl) A01 = 1.f;
                if (c0     == rBl) A10 = 1.f;
                if (c0 + 1 == rBl) A11 = 1.f;
                if (c0 + 8 == rAl) B00 = 1.f;
                if (c0 + 9 == rAl) B01 = 1.f;
                if (c0 + 8 == rBl) B10 = 1.f;
                if (c0 + 9 == rBl) B11 = 1.f;
            }

            uint32_t a[4];
            a[0] = h2(A00, A01);
            a[1] = h2(A10, A11);
            a[2] = h2(B00, B01);
            a[3] = h2(B10, B11);

#pragma unroll
            for (int p = 0; p < 4; p++) {
                uint32_t bb[4];
                ldsm_x4_t(bb, pvBase + ks * (16 * XSTRIDE * 2) + p * 32);
                mma16816(C[rg][2 * p],     a, bb[0], bb[1]);
                mma16816(C[rg][2 * p + 1], a, bb[2], bb[3]);
            }
        }
    }
}

// ================= k2: S-MMA + sigmoid + PV-MMA =================
// grid (64, SPLIT), 128 threads = 4 warps x 32 rows.
__global__ __launch_bounds__(128, 4) void k2_aggregate(
    const float* __restrict__ temp_p,
    const float* __restrict__ theta_p)
{
    __shared__ __align__(16) __half sB[128 * XSTRIDE];   // x tile [j][64+pad]
    __shared__ __align__(16) __half szh[128 * ZSTRIDE];  // z hi [j][16+pad]
    __shared__ __align__(16) __half szl[128 * ZSTRIDE];  // z lo
    __shared__ float stq[128];

    const int tid  = threadIdx.x;
    const int wid  = tid >> 5;
    const int lane = tid & 31;
    const int g = lane >> 2;
    const int t = lane & 3;

    const int rowBase = blockIdx.x * 128;
    const int jbase0  = blockIdx.y * JCHUNK;

    const float L2E   = 1.4426950408889634f;
    const float temp  = *temp_p;
    const float thL   = (*theta_p) * L2E;
    const float mS    = -2.f * temp * L2E;

    // row-side fragments + constants (live whole kernel)
    uint32_t aih[2][4], ail[2][4];
    float cr[2][2];
#pragma unroll
    for (int rg = 0; rg < 2; rg++) {
        int R  = rowBase + wid * 32 + rg * 16;
        int rA = R + g, rB = R + g + 8;
        aih[rg][0] = ld32g(g_zh + (size_t)rA * 16 + 2 * t);
        aih[rg][1] = ld32g(g_zh + (size_t)rB * 16 + 2 * t);
        aih[rg][2] = ld32g(g_zh + (size_t)rA * 16 + 2 * t + 8);
        aih[rg][3] = ld32g(g_zh + (size_t)rB * 16 + 2 * t + 8);
        ail[rg][0] = ld32g(g_zl + (size_t)rA * 16 + 2 * t);
        ail[rg][1] = ld32g(g_zl + (size_t)rB * 16 + 2 * t);
        ail[rg][2] = ld32g(g_zl + (size_t)rA * 16 + 2 * t + 8);
        ail[rg][3] = ld32g(g_zl + (size_t)rB * 16 + 2 * t + 8);
        cr[rg][0] = g_tq[rA] - thL;
        cr[rg][1] = g_tq[rB] - thL;
    }

    float C[2][8][4];
#pragma unroll
    for (int rg = 0; rg < 2; rg++)
#pragma unroll
        for (int nt = 0; nt < 8; nt++)
#pragma unroll
            for (int c = 0; c < 4; c++) C[rg][nt][c] = 0.f;

    // per-lane ldmatrix base addresses
    const int lr = lane & 7;
    const int m4 = lane >> 3;
    const uint32_t pvBase = smem_u32(sB) +
        2 * (((m4 & 1) * 8 + lr) * XSTRIDE + (m4 >> 1) * 8);
    const int lz = lane & 15;
    const uint32_t zoff = 2 * ((lz & 7) * ZSTRIDE + ((lz >> 3) & 1) * 8);
    const uint32_t zhBase = smem_u32(szh) + zoff;
    const uint32_t zlBase = smem_u32(szl) + zoff;

    for (int tl = 0; tl < TILES; ++tl) {
        const int jbase = jbase0 + tl * 128;
        __syncthreads();
        // cooperative tile loads: row = tid
        {
            const uint4* xs = (const uint4*)(g_x16 + (size_t)(jbase + tid) * 64);
            uint4* xd = (uint4*)(sB + tid * XSTRIDE);
#pragma unroll
            for (int q = 0; q < 8; q++) xd[q] = xs[q];
            const uint4* hs = (const uint4*)(g_zh + (size_t)(jbase + tid) * 16);
            uint4* hd = (uint4*)(szh + tid * ZSTRIDE);
            hd[0] = hs[0]; hd[1] = hs[1];
            const uint4* ls = (const uint4*)(g_zl + (size_t)(jbase + tid) * 16);
            uint4* ld = (uint4*)(szl + tid * ZSTRIDE);
            ld[0] = ls[0]; ld[1] = ls[1];
            stq[tid] = g_tq[jbase + tid];
        }
        __syncthreads();

        if (jbase == rowBase)
            k2_tile<true >(pvBase, zhBase, zlBase, stq, aih, ail, cr, mS, wid, g, t, C);
        else
            k2_tile<false>(pvBase, zhBase, zlBase, stq, aih, ail, cr, mS, wid, g, t, C);
    }

    // store partials: [split][row][64]
#pragma unroll
    for (int rg = 0; rg < 2; rg++) {
        int rA = rowBase + wid * 32 + rg * 16 + g;
        float* b0 = g_part + ((size_t)blockIdx.y * N + rA) * 64;
        float* b1 = b0 + (size_t)8 * 64;
#pragma unroll
        for (int nt = 0; nt < 8; nt++) {
            int col = nt * 8 + 2 * t;
            *(float2*)(b0 + col) = make_float2(C[rg][nt][0], C[rg][nt][1]);
            *(float2*)(b1 + col) = make_float2(C[rg][nt][2], C[rg][nt][3]);
        }
    }
}

// ================= k3: reduce -> normalize -> fc3 -> fc6 -> softmax =================
__global__ __launch_bounds__(128) void k3_head(
    const float* __restrict__ w3, const float* __restrict__ b3,
    const float* __restrict__ w6, const float* __restrict__ b6,
    float* __restrict__ out)
{
    __shared__ float sw3[8 * 60], sb3[8], sw6[10 * 8], sb6[10];
    int tid = threadIdx.x;
    for (int idx = tid; idx < 480; idx += 128) sw3[idx] = w3[idx];
    if (tid < 8)  sb3[tid] = b3[tid];
    if (tid < 80) sw6[tid] = w6[tid];
    if (tid < 10) sb6[tid] = b6[tid];
    __syncthreads();

    int r = blockIdx.x * 128 + tid;

    float h[64];
#pragma unroll
    for (int c = 0; c < 64; c++) h[c] = 0.f;
#pragma unroll
    for (int s = 0; s < SPLIT; s++) {
        const float4* p = (const float4*)(g_part + ((size_t)s * N + r) * 64);
#pragma unroll
        for (int q = 0; q < 16; q++) {
            float4 v = p[q];
            h[4 * q + 0] += v.x; h[4 * q + 1] += v.y;
            h[4 * q + 2] += v.z; h[4 * q + 3] += v.w;
        }
    }
    float inv = 1.f / h[60];
#pragma unroll
    for (int c = 0; c < 60; c++) h[c] *= inv;

    float tv[8];
#pragma unroll
    for (int o = 0; o < 8; o++) {
        float s = sb3[o];
#pragma unroll
        for (int k = 0; k < 60; k++) s = fmaf(sw3[o * 60 + k], h[k], s);
        tv[o] = s;
    }

    float u[10];
    float m = -1e30f;
#pragma unroll
    for (int c = 0; c < 10; c++) {
        float s = sb6[c];
#pragma unroll
        for (int o = 0; o < 8; o++) s = fmaf(sw6[c * 8 + o], tv[o], s);
        u[c] = s;
        m = fmaxf(m, s);
    }
    float denom = 0.f;
#pragma unroll
    for (int c = 0; c < 10; c++) { u[c] = __expf(u[c] - m); denom += u[c]; }
    float dinv = 1.f / denom;
#pragma unroll
    for (int c = 0; c < 10; c++) out[r * 10 + c] = u[c] * dinv;
}

// ================= launch =================
extern "C" void kernel_launch(void* const* d_in, const int* in_sizes, int n_in,
                              void* d_out, int out_size)
{
    const float* x     = (const float*)d_in[0];
    const float* w1    = (const float*)d_in[1];
    const float* b1    = (const float*)d_in[2];
    const float* w2    = (const float*)d_in[3];
    const float* b2    = (const float*)d_in[4];
    const float* w3    = (const float*)d_in[5];
    const float* b3    = (const float*)d_in[6];
    const float* w6    = (const float*)d_in[7];
    const float* b6    = (const float*)d_in[8];
    const float* temp  = (const float*)d_in[9];
    const float* theta = (const float*)d_in[10];
    float* out = (float*)d_out;

    k1_embed<<<N / 64, 128>>>(x, w1, b1, w2, b2, temp);
    dim3 g2(N / 128, SPLIT);
    k2_aggregate<<<g2, 128>>>(temp, theta);
    k3_head<<<N / 128, 128>>>(w3, b3, w6, b6, out);
}

// round 5
// speedup vs baseline: 3.8064x; 1.0216x over previous
#include <cuda_runtime.h>
#include <cuda_fp16.h>
#include <cstdint>

#define N       8192
#define SPLIT   8
#define JCHUNK  (N / SPLIT)     // 1024
#define TILES   (JCHUNK / 128)  // 8
#define XSTRIDE 72              // sB row stride (halves): 64 + 8 pad
#define ZSTRIDE 24              // z tile row stride (halves): 16 + 8 pad

// ---------------- scratch (no allocs allowed) ----------------
__device__ __half g_x16[N * 64];        // [r][0..59]=x, [60]=1, [61..63]=0
__device__ __half g_zh[N * 16];         // z hi (fp16)
__device__ __half g_zl[N * 16];         // z lo (fp16 residual)
__device__ float  g_tq[N];              // temp*log2e*||z||^2
__device__ float  g_W[976];             // W21 (16x60) + b21 (16)
__device__ float  g_part[SPLIT * N * 64];

// ---------------- helpers ----------------
static __device__ __forceinline__ uint32_t smem_u32(const void* p) {
    uint32_t a;
    asm("{ .reg .u64 t; cvta.to.shared.u64 t, %1; cvt.u32.u64 %0, t; }" : "=r"(a) : "l"(p));
    return a;
}
static __device__ __forceinline__ void mma16816(float c[4], const uint32_t a[4],
                                                uint32_t b0, uint32_t b1) {
    asm volatile(
        "mma.sync.aligned.m16n8k16.row.col.f32.f16.f16.f32 "
        "{%0,%1,%2,%3}, {%4,%5,%6,%7}, {%8,%9}, {%0,%1,%2,%3};"
        : "+f"(c[0]), "+f"(c[1]), "+f"(c[2]), "+f"(c[3])
        : "r"(a[0]), "r"(a[1]), "r"(a[2]), "r"(a[3]), "r"(b0), "r"(b1));
}
static __device__ __forceinline__ void ldsm_x2(uint32_t r[2], uint32_t addr) {
    asm volatile("ldmatrix.sync.aligned.m8n8.x2.shared.b16 {%0,%1}, [%2];"
                 : "=r"(r[0]), "=r"(r[1]) : "r"(addr));
}
static __device__ __forceinline__ void ldsm_x4_t(uint32_t r[4], uint32_t addr) {
    asm volatile("ldmatrix.sync.aligned.m8n8.x4.trans.shared.b16 {%0,%1,%2,%3}, [%4];"
                 : "=r"(r[0]), "=r"(r[1]), "=r"(r[2]), "=r"(r[3]) : "r"(addr));
}
static __device__ __forceinline__ uint32_t ld32g(const __half* p) {
    return *reinterpret_cast<const uint32_t*>(p);
}
static __device__ __forceinline__ uint32_t h2bits(__half2 v) {
    return *reinterpret_cast<uint32_t*>(&v);
}

// ================= k0: fold fc1/fc2 -> W21 (16x60), b21 =================
__global__ __launch_bounds__(128) void k0_fold(
    const float* __restrict__ w1, const float* __restrict__ b1,
    const float* __restrict__ w2, const float* __restrict__ b2)
{
    __shared__ float sw1[32 * 60], sw2[16 * 32], sb1[32];
    int tid = threadIdx.x;
    for (int i = tid; i < 32 * 60; i += 128) sw1[i] = w1[i];
    for (int i = tid; i < 16 * 32; i += 128) sw2[i] = w2[i];
    if (tid < 32) sb1[tid] = b1[tid];
    __syncthreads();
    for (int e = tid; e < 960; e += 128) {
        int o = e / 60, k = e % 60;
        float s = 0.f;
#pragma unroll
        for (int m = 0; m < 32; m++) s = fmaf(sw2[o * 32 + m], sw1[m * 60 + k], s);
        g_W[e] = s;
    }
    if (tid < 16) {
        float s = b2[tid];
#pragma unroll
        for (int m = 0; m < 32; m++) s = fmaf(sw2[tid * 32 + m], sb1[m], s);
        g_W[960 + tid] = s;
    }
}

// ================= k1: z = W21 x + b21, split hi/lo, x fp16, tq =================
// 256 thr/block, 32 rows/block (8 threads per row), grid 256.
__global__ __launch_bounds__(256) void k1_embed(
    const float* __restrict__ x,
    const float* __restrict__ temp_p)
{
    __shared__ __align__(16) float sx[32 * 60];
    __shared__ __align__(16) float sWb[976];
    int tid = threadIdx.x;
    int rows0 = blockIdx.x * 32;

    for (int e = tid; e < 1920; e += 256) sx[e] = x[(size_t)rows0 * 60 + e];
    for (int e = tid; e < 976; e += 256) sWb[e] = g_W[e];
    __syncthreads();

    int r = tid >> 3, s = tid & 7;
    const float* xr = sx + r * 60;
    const float* w0 = sWb + (2 * s) * 60;
    const float* w1p = sWb + (2 * s + 1) * 60;

    float z0 = sWb[960 + 2 * s], z1 = sWb[960 + 2 * s + 1];
#pragma unroll
    for (int q = 0; q < 15; q++) {
        float4 xa = *(const float4*)(xr + 4 * q);
        float4 a = *(const float4*)(w0 + 4 * q);
        float4 b = *(const float4*)(w1p + 4 * q);
        z0 = fmaf(a.x, xa.x, z0); z1 = fmaf(b.x, xa.x, z1);
        z0 = fmaf(a.y, xa.y, z0); z1 = fmaf(b.y, xa.y, z1);
        z0 = fmaf(a.z, xa.z, z0); z1 = fmaf(b.z, xa.z, z1);
        z0 = fmaf(a.w, xa.w, z0); z1 = fmaf(b.w, xa.w, z1);
    }

    float sq = fmaf(z0, z0, z1 * z1);
    sq += __shfl_xor_sync(0xffffffffu, sq, 1);
    sq += __shfl_xor_sync(0xffffffffu, sq, 2);
    sq += __shfl_xor_sync(0xffffffffu, sq, 4);

    int R = rows0 + r;
    if (s == 0) g_tq[R] = (*temp_p) * 1.4426950408889634f * sq;

    __half h0 = __float2half_rn(z0), h1 = __float2half_rn(z1);
    __half l0 = __float2half_rn(z0 - __half2float(h0));
    __half l1 = __float2half_rn(z1 - __half2float(h1));
    *(uint32_t*)(g_zh + (size_t)R * 16 + 2 * s) = h2bits(__halves2half2(h0, h1));
    *(uint32_t*)(g_zl + (size_t)R * 16 + 2 * s) = h2bits(__halves2half2(l0, l1));

    union { __half h[8]; uint4 v; } xo;
    if (s < 7) {
#pragma unroll
        for (int f = 0; f < 8; f++) xo.h[f] = __float2half_rn(xr[8 * s + f]);
    } else {
        xo.h[0] = __float2half_rn(xr[56]);
        xo.h[1] = __float2half_rn(xr[57]);
        xo.h[2] = __float2half_rn(xr[58]);
        xo.h[3] = __float2half_rn(xr[59]);
        xo.h[4] = __float2half_rn(1.0f);
        xo.h[5] = __float2half_rn(0.0f);
        xo.h[6] = __float2half_rn(0.0f);
        xo.h[7] = __float2half_rn(0.0f);
    }
    *(uint4*)(g_x16 + (size_t)R * 64 + 8 * s) = xo.v;
}

// ---------------- k2 per-tile body ----------------
template <bool DIAG>
static __device__ __forceinline__ void k2_tile(
    uint32_t pvBase, uint32_t zhBase, const float* stq,
    const uint32_t aih[2][4], const uint32_t ail[2][4], const float rc[2][2],
    float pS, int wid, int g, int t, float C[2][8][4])
{
    const __half2 ones = __floats2half2_rn(1.f, 1.f);
    const __half  oneh = __float2half(1.f);
#pragma unroll
    for (int ks = 0; ks < 8; ks++) {
        float2 tqa = *(const float2*)(stq + ks * 16 + 2 * t);
        float2 tqb = *(const float2*)(stq + ks * 16 + 8 + 2 * t);
        uint32_t zh0[2], zh1[2];
        ldsm_x2(zh0, zhBase + (ks * 16 + 0) * (ZSTRIDE * 2));
        ldsm_x2(zh1, zhBase + (ks * 16 + 8) * (ZSTRIDE * 2));
#pragma unroll
        for (int rg = 0; rg < 2; rg++) {
            float S0[4] = {0.f, 0.f, 0.f, 0.f};
            float S1[4] = {0.f, 0.f, 0.f, 0.f};
            mma16816(S0, aih[rg], zh0[0], zh0[1]);   // hi_i * hi_j
            mma16816(S0, ail[rg], zh0[0], zh0[1]);   // lo_i * hi_j
            mma16816(S1, aih[rg], zh1[0], zh1[1]);
            mma16816(S1, ail[rg], zh1[0], zh1[1]);

            const float rA = rc[rg][0], rB = rc[rg][1];
            // w = L2E*(theta - temp*dist) = pS*S + (thL - tq_i) - tq_j
            __half2 wA0 = __floats2half2_rn(fmaf(pS, S0[0], rA) - tqa.x,
                                            fmaf(pS, S0[1], rA) - tqa.y);
            __half2 wB0 = __floats2half2_rn(fmaf(pS, S0[2], rB) - tqa.x,
                                            fmaf(pS, S0[3], rB) - tqa.y);
            __half2 wA1 = __floats2half2_rn(fmaf(pS, S1[0], rA) - tqb.x,
                                            fmaf(pS, S1[1], rA) - tqb.y);
            __half2 wB1 = __floats2half2_rn(fmaf(pS, S1[2], rB) - tqb.x,
                                            fmaf(pS, S1[3], rB) - tqb.y);
            // A = e/(1+e), e = 2^w  (w <= thL ~ 1.5 -> no overflow; underflow -> A=0)
            __half2 eA0 = h2exp2(wA0), eB0 = h2exp2(wB0);
            __half2 eA1 = h2exp2(wA1), eB1 = h2exp2(wB1);
            __half2 AA0 = __hmul2(eA0, h2rcp(__hadd2(ones, eA0)));
            __half2 AB0 = __hmul2(eB0, h2rcp(__hadd2(ones, eB0)));
            __half2 AA1 = __hmul2(eA1, h2rcp(__hadd2(ones, eA1)));
            __half2 AB1 = __hmul2(eB1, h2rcp(__hadd2(ones, eB1)));

            if (DIAG) {
                int rAl = wid * 32 + rg * 16 + g;
                int rBl = rAl + 8;
                int c0 = ks * 16 + 2 * t;
                if (c0     == rAl) AA0 = __halves2half2(oneh, __high2half(AA0));
                if (c0 + 1 == rAl) AA0 = __halves2half2(__low2half(AA0), oneh);
                if (c0     == rBl) AB0 = __halves2half2(oneh, __high2half(AB0));
                if (c0 + 1 == rBl) AB0 = __halves2half2(__low2half(AB0), oneh);
                if (c0 + 8 == rAl) AA1 = __halves2half2(oneh, __high2half(AA1));
                if (c0 + 9 == rAl) AA1 = __halves2half2(__low2half(AA1), oneh);
                if (c0 + 8 == rBl) AB1 = __halves2half2(oneh, __high2half(AB1));
                if (c0 + 9 == rBl) AB1 = __halves2half2(__low2half(AB1), oneh);
            }

            uint32_t a[4];
            a[0] = h2bits(AA0);
            a[1] = h2bits(AB0);
            a[2] = h2bits(AA1);
            a[3] = h2bits(AB1);

#pragma unroll
            for (int p = 0; p < 4; p++) {
                uint32_t bb[4];
                ldsm_x4_t(bb, pvBase + ks * (16 * XSTRIDE * 2) + p * 32);
                mma16816(C[rg][2 * p],     a, bb[0], bb[1]);
                mma16816(C[rg][2 * p + 1], a, bb[2], bb[3]);
            }
        }
    }
}

// ================= k2: S-MMA + f16x2 sigmoid + PV-MMA =================
__global__ __launch_bounds__(128) void k2_aggregate(
    const float* __restrict__ temp_p,
    const float* __restrict__ theta_p)
{
    __shared__ __align__(16) __half sB[128 * XSTRIDE];   // x tile [j][64+pad]
    __shared__ __align__(16) __half szh[128 * ZSTRIDE];  // z hi [j][16+pad]
    __shared__ float stq[128];

    const int tid  = threadIdx.x;
    const int wid  = tid >> 5;
    const int lane = tid & 31;
    const int g = lane >> 2;
    const int t = lane & 3;

    const int rowBase = blockIdx.x * 128;
    const int jbase0  = blockIdx.y * JCHUNK;

    const float L2E  = 1.4426950408889634f;
    const float temp = *temp_p;
    const float thL  = (*theta_p) * L2E;
    const float pS   = 2.f * temp * L2E;

    uint32_t aih[2][4], ail[2][4];
    float rc[2][2];
#pragma unroll
    for (int rg = 0; rg < 2; rg++) {
        int R  = rowBase + wid * 32 + rg * 16;
        int rA = R + g, rB = R + g + 8;
        aih[rg][0] = ld32g(g_zh + (size_t)rA * 16 + 2 * t);
        aih[rg][1] = ld32g(g_zh + (size_t)rB * 16 + 2 * t);
        aih[rg][2] = ld32g(g_zh + (size_t)rA * 16 + 2 * t + 8);
        aih[rg][3] = ld32g(g_zh + (size_t)rB * 16 + 2 * t + 8);
        ail[rg][0] = ld32g(g_zl + (size_t)rA * 16 + 2 * t);
        ail[rg][1] = ld32g(g_zl + (size_t)rB * 16 + 2 * t);
        ail[rg][2] = ld32g(g_zl + (size_t)rA * 16 + 2 * t + 8);
        ail[rg][3] = ld32g(g_zl + (size_t)rB * 16 + 2 * t + 8);
        rc[rg][0] = thL - g_tq[rA];
        rc[rg][1] = thL - g_tq[rB];
    }

    float C[2][8][4];
#pragma unroll
    for (int rg = 0; rg < 2; rg++)
#pragma unroll
        for (int nt = 0; nt < 8; nt++)
#pragma unroll
            for (int c = 0; c < 4; c++) C[rg][nt][c] = 0.f;

    const int lr = lane & 7;
    const int m4 = lane >> 3;
    const uint32_t pvBase = smem_u32(sB) +
        2 * (((m4 & 1) * 8 + lr) * XSTRIDE + (m4 >> 1) * 8);
    const int lz = lane & 15;
    const uint32_t zhBase = smem_u32(szh) +
        2 * ((lz & 7) * ZSTRIDE + ((lz >> 3) & 1) * 8);

    for (int tl = 0; tl < TILES; ++tl) {
        const int jbase = jbase0 + tl * 128;
        __syncthreads();
        {
            const uint4* xs = (const uint4*)(g_x16 + (size_t)(jbase + tid) * 64);
            uint4* xd = (uint4*)(sB + tid * XSTRIDE);
#pragma unroll
            for (int q = 0; q < 8; q++) xd[q] = xs[q];
            const uint4* hs = (const uint4*)(g_zh + (size_t)(jbase + tid) * 16);
            uint4* hd = (uint4*)(szh + tid * ZSTRIDE);
            hd[0] = hs[0]; hd[1] = hs[1];
            stq[tid] = g_tq[jbase + tid];
        }
        __syncthreads();

        if (jbase == rowBase)
            k2_tile<true >(pvBase, zhBase, stq, aih, ail, rc, pS, wid, g, t, C);
        else
            k2_tile<false>(pvBase, zhBase, stq, aih, ail, rc, pS, wid, g, t, C);
    }

    // store partials: [split][row][64]
#pragma unroll
    for (int rg = 0; rg < 2; rg++) {
        int rA = rowBase + wid * 32 + rg * 16 + g;
        float* b0 = g_part + ((size_t)blockIdx.y * N + rA) * 64;
        float* b1 = b0 + (size_t)8 * 64;
#pragma unroll
        for (int nt = 0; nt < 8; nt++) {
            int col = nt * 8 + 2 * t;
            *(float2*)(b0 + col) = make_float2(C[rg][nt][0], C[rg][nt][1]);
            *(float2*)(b1 + col) = make_float2(C[rg][nt][2], C[rg][nt][3]);
        }
    }
}

// ================= k3: reduce -> normalize -> fc3 -> fc6 -> softmax =================
__global__ __launch_bounds__(128) void k3_head(
    const float* __restrict__ w3, const float* __restrict__ b3,
    const float* __restrict__ w6, const float* __restrict__ b6,
    float* __restrict__ out)
{
    __shared__ float sw3[8 * 60], sb3[8], sw6[10 * 8], sb6[10];
    int tid = threadIdx.x;
    for (int idx = tid; idx < 480; idx += 128) sw3[idx] = w3[idx];
    if (tid < 8)  sb3[tid] = b3[tid];
    if (tid < 80) sw6[tid] = w6[tid];
    if (tid < 10) sb6[tid] = b6[tid];
    __syncthreads();

    int r = blockIdx.x * 128 + tid;

    float h[64];
#pragma unroll
    for (int c = 0; c < 64; c++) h[c] = 0.f;
#pragma unroll
    for (int s = 0; s < SPLIT; s++) {
        const float4* p = (const float4*)(g_part + ((size_t)s * N + r) * 64);
#pragma unroll
        for (int q = 0; q < 16; q++) {
            float4 v = p[q];
            h[4 * q + 0] += v.x; h[4 * q + 1] += v.y;
            h[4 * q + 2] += v.z; h[4 * q + 3] += v.w;
        }
    }
    float inv = 1.f / h[60];
#pragma unroll
    for (int c = 0; c < 60; c++) h[c] *= inv;

    float tv[8];
#pragma unroll
    for (int o = 0; o < 8; o++) {
        float s = sb3[o];
#pragma unroll
        for (int k = 0; k < 60; k++) s = fmaf(sw3[o * 60 + k], h[k], s);
        tv[o] = s;
    }

    float u[10];
    float m = -1e30f;
#pragma unroll
    for (int c = 0; c < 10; c++) {
        float s = sb6[c];
#pragma unroll
        for (int o = 0; o < 8; o++) s = fmaf(sw6[c * 8 + o], tv[o], s);
        u[c] = s;
        m = fmaxf(m, s);
    }
    float denom = 0.f;
#pragma unroll
    for (int c = 0; c < 10; c++) { u[c] = __expf(u[c] - m); denom += u[c]; }
    float dinv = 1.f / denom;
#pragma unroll
    for (int c = 0; c < 10; c++) out[r * 10 + c] = u[c] * dinv;
}

// ================= launch =================
extern "C" void kernel_launch(void* const* d_in, const int* in_sizes, int n_in,
                              void* d_out, int out_size)
{
    const float* x     = (const float*)d_in[0];
    const float* w1    = (const float*)d_in[1];
    const float* b1    = (const float*)d_in[2];
    const float* w2    = (const float*)d_in[3];
    const float* b2    = (const float*)d_in[4];
    const float* w3    = (const float*)d_in[5];
    const float* b3    = (const float*)d_in[6];
    const float* w6    = (const float*)d_in[7];
    const float* b6    = (const float*)d_in[8];
    const float* temp  = (const float*)d_in[9];
    const float* theta = (const float*)d_in[10];
    float* out = (float*)d_out;

    k0_fold<<<1, 128>>>(w1, b1, w2, b2);
    k1_embed<<<N / 32, 256>>>(x, temp);
    dim3 g2(N / 128, SPLIT);
    k2_aggregate<<<g2, 128>>>(temp, theta);
    k3_head<<<N / 128, 128>>>(w3, b3, w6, b6, out);
}

// round 6
// speedup vs baseline: 4.3738x; 1.1491x over previous
#include <cuda_runtime.h>
#include <cuda_fp16.h>
#include <cstdint>

#define N       8192
#define SPLIT   8
#define JCHUNK  (N / SPLIT)     // 1024
#define TILES   (JCHUNK / 128)  // 8
#define XSTRIDE 72              // sB row stride (halves): 64 + 8 pad
#define ZSTRIDE 24              // z tile row stride (halves): 16 + 8 pad

// ---------------- scratch (no allocs allowed) ----------------
__device__ __half g_x16[N * 64];        // [r][0..59]=x, [60]=1, [61..63]=0
__device__ __half g_zh[N * 16];         // z hi (fp16)
__device__ __half g_zl[N * 16];         // z lo (fp16 residual)
__device__ float  g_tq[N];              // temp*log2e*||z||^2
__device__ float  g_part[SPLIT * N * 64];

// ---------------- helpers ----------------
static __device__ __forceinline__ uint32_t smem_u32(const void* p) {
    uint32_t a;
    asm("{ .reg .u64 t; cvta.to.shared.u64 t, %1; cvt.u32.u64 %0, t; }" : "=r"(a) : "l"(p));
    return a;
}
static __device__ __forceinline__ void mma16816(float c[4], const uint32_t a[4],
                                                uint32_t b0, uint32_t b1) {
    asm volatile(
        "mma.sync.aligned.m16n8k16.row.col.f32.f16.f16.f32 "
        "{%0,%1,%2,%3}, {%4,%5,%6,%7}, {%8,%9}, {%0,%1,%2,%3};"
        : "+f"(c[0]), "+f"(c[1]), "+f"(c[2]), "+f"(c[3])
        : "r"(a[0]), "r"(a[1]), "r"(a[2]), "r"(a[3]), "r"(b0), "r"(b1));
}
static __device__ __forceinline__ void ldsm_x2(uint32_t r[2], uint32_t addr) {
    asm volatile("ldmatrix.sync.aligned.m8n8.x2.shared.b16 {%0,%1}, [%2];"
                 : "=r"(r[0]), "=r"(r[1]) : "r"(addr));
}
static __device__ __forceinline__ void ldsm_x4_t(uint32_t r[4], uint32_t addr) {
    asm volatile("ldmatrix.sync.aligned.m8n8.x4.trans.shared.b16 {%0,%1,%2,%3}, [%4];"
                 : "=r"(r[0]), "=r"(r[1]), "=r"(r[2]), "=r"(r[3]) : "r"(addr));
}
static __device__ __forceinline__ uint32_t ld32g(const __half* p) {
    return *reinterpret_cast<const uint32_t*>(p);
}
static __device__ __forceinline__ uint32_t h2bits(__half2 v) {
    return *reinterpret_cast<uint32_t*>(&v);
}

// ================= k1: fold fc1/fc2 per-block, z = W21 x + b21, split hi/lo =================
// 256 thr/block, 32 rows/block, grid 256.
__global__ __launch_bounds__(256) void k1_embed(
    const float* __restrict__ x,
    const float* __restrict__ w1, const float* __restrict__ b1,
    const float* __restrict__ w2, const float* __restrict__ b2,
    const float* __restrict__ temp_p)
{
    __shared__ __align__(16) float sbuf[1920];   // w1, then x tile
    __shared__ __align__(16) float sw2[512];
    __shared__ __align__(16) float sWb[976];     // W21 (960) + b21 (16)
    __shared__ float sb1[32];
    int tid = threadIdx.x;
    int rows0 = blockIdx.x * 32;

    for (int e = tid; e < 1920; e += 256) sbuf[e] = w1[e];
    for (int e = tid; e < 512; e += 256) sw2[e] = w2[e];
    if (tid < 32) sb1[tid] = b1[tid];
    __syncthreads();

    // W21 = W2 @ W1, b21 = W2 @ b1 + b2 (redundant per block, cheap)
    for (int e = tid; e < 960; e += 256) {
        int o = e / 60, k = e % 60;
        float s = 0.f;
#pragma unroll
        for (int m = 0; m < 32; m++) s = fmaf(sw2[o * 32 + m], sbuf[m * 60 + k], s);
        sWb[e] = s;
    }
    if (tid < 16) {
        float s = b2[tid];
#pragma unroll
        for (int m = 0; m < 32; m++) s = fmaf(sw2[tid * 32 + m], sb1[m], s);
        sWb[960 + tid] = s;
    }
    __syncthreads();

    for (int e = tid; e < 1920; e += 256) sbuf[e] = x[(size_t)rows0 * 60 + e];
    __syncthreads();

    int r = tid >> 3, s = tid & 7;
    const float* xr = sbuf + r * 60;
    const float* w0p = sWb + (2 * s) * 60;
    const float* w1p = sWb + (2 * s + 1) * 60;

    float z0 = sWb[960 + 2 * s], z1 = sWb[960 + 2 * s + 1];
#pragma unroll
    for (int q = 0; q < 15; q++) {
        float4 xa = *(const float4*)(xr + 4 * q);
        float4 a = *(const float4*)(w0p + 4 * q);
        float4 b = *(const float4*)(w1p + 4 * q);
        z0 = fmaf(a.x, xa.x, z0); z1 = fmaf(b.x, xa.x, z1);
        z0 = fmaf(a.y, xa.y, z0); z1 = fmaf(b.y, xa.y, z1);
        z0 = fmaf(a.z, xa.z, z0); z1 = fmaf(b.z, xa.z, z1);
        z0 = fmaf(a.w, xa.w, z0); z1 = fmaf(b.w, xa.w, z1);
    }

    float sq = fmaf(z0, z0, z1 * z1);
    sq += __shfl_xor_sync(0xffffffffu, sq, 1);
    sq += __shfl_xor_sync(0xffffffffu, sq, 2);
    sq += __shfl_xor_sync(0xffffffffu, sq, 4);

    int R = rows0 + r;
    if (s == 0) g_tq[R] = (*temp_p) * 1.4426950408889634f * sq;

    __half h0 = __float2half_rn(z0), h1 = __float2half_rn(z1);
    __half l0 = __float2half_rn(z0 - __half2float(h0));
    __half l1 = __float2half_rn(z1 - __half2float(h1));
    *(uint32_t*)(g_zh + (size_t)R * 16 + 2 * s) = h2bits(__halves2half2(h0, h1));
    *(uint32_t*)(g_zl + (size_t)R * 16 + 2 * s) = h2bits(__halves2half2(l0, l1));

    union { __half h[8]; uint4 v; } xo;
    if (s < 7) {
#pragma unroll
        for (int f = 0; f < 8; f++) xo.h[f] = __float2half_rn(xr[8 * s + f]);
    } else {
        xo.h[0] = __float2half_rn(xr[56]);
        xo.h[1] = __float2half_rn(xr[57]);
        xo.h[2] = __float2half_rn(xr[58]);
        xo.h[3] = __float2half_rn(xr[59]);
        xo.h[4] = __float2half_rn(1.0f);
        xo.h[5] = __float2half_rn(0.0f);
        xo.h[6] = __float2half_rn(0.0f);
        xo.h[7] = __float2half_rn(0.0f);
    }
    *(uint4*)(g_x16 + (size_t)R * 64 + 8 * s) = xo.v;
}

// ---------------- k2 per-tile body ----------------
template <bool DIAG>
static __device__ __forceinline__ void k2_tile(
    uint32_t pvBase, uint32_t zhBase, const float* stq,
    const uint32_t aih[2][4], const uint32_t ail[2][4], const float rc[2][2],
    float pS, int wid, int g, int t, float C[2][8][4])
{
    const __half2 ones = __floats2half2_rn(1.f, 1.f);
    const __half  oneh = __float2half(1.f);
#pragma unroll
    for (int ks = 0; ks < 8; ks++) {
        float2 tqa = *(const float2*)(stq + ks * 16 + 2 * t);
        float2 tqb = *(const float2*)(stq + ks * 16 + 8 + 2 * t);
        uint32_t zh0[2], zh1[2];
        ldsm_x2(zh0, zhBase + (ks * 16 + 0) * (ZSTRIDE * 2));
        ldsm_x2(zh1, zhBase + (ks * 16 + 8) * (ZSTRIDE * 2));
#pragma unroll
        for (int rg = 0; rg < 2; rg++) {
            float S0[4] = {0.f, 0.f, 0.f, 0.f};
            float S1[4] = {0.f, 0.f, 0.f, 0.f};
            mma16816(S0, aih[rg], zh0[0], zh0[1]);   // hi_i * hi_j
            mma16816(S0, ail[rg], zh0[0], zh0[1]);   // lo_i * hi_j
            mma16816(S1, aih[rg], zh1[0], zh1[1]);
            mma16816(S1, ail[rg], zh1[0], zh1[1]);

            const float rA = rc[rg][0], rB = rc[rg][1];
            __half2 wA0 = __floats2half2_rn(fmaf(pS, S0[0], rA) - tqa.x,
                                            fmaf(pS, S0[1], rA) - tqa.y);
            __half2 wB0 = __floats2half2_rn(fmaf(pS, S0[2], rB) - tqa.x,
                                            fmaf(pS, S0[3], rB) - tqa.y);
            __half2 wA1 = __floats2half2_rn(fmaf(pS, S1[0], rA) - tqb.x,
                                            fmaf(pS, S1[1], rA) - tqb.y);
            __half2 wB1 = __floats2half2_rn(fmaf(pS, S1[2], rB) - tqb.x,
                                            fmaf(pS, S1[3], rB) - tqb.y);
            __half2 eA0 = h2exp2(wA0), eB0 = h2exp2(wB0);
            __half2 eA1 = h2exp2(wA1), eB1 = h2exp2(wB1);
            __half2 AA0 = __hmul2(eA0, h2rcp(__hadd2(ones, eA0)));
            __half2 AB0 = __hmul2(eB0, h2rcp(__hadd2(ones, eB0)));
            __half2 AA1 = __hmul2(eA1, h2rcp(__hadd2(ones, eA1)));
            __half2 AB1 = __hmul2(eB1, h2rcp(__hadd2(ones, eB1)));

            if (DIAG) {
                int rAl = wid * 32 + rg * 16 + g;
                int rBl = rAl + 8;
                int c0 = ks * 16 + 2 * t;
                if (c0     == rAl) AA0 = __halves2half2(oneh, __high2half(AA0));
                if (c0 + 1 == rAl) AA0 = __halves2half2(__low2half(AA0), oneh);
                if (c0     == rBl) AB0 = __halves2half2(oneh, __high2half(AB0));
                if (c0 + 1 == rBl) AB0 = __halves2half2(__low2half(AB0), oneh);
                if (c0 + 8 == rAl) AA1 = __halves2half2(oneh, __high2half(AA1));
                if (c0 + 9 == rAl) AA1 = __halves2half2(__low2half(AA1), oneh);
                if (c0 + 8 == rBl) AB1 = __halves2half2(oneh, __high2half(AB1));
                if (c0 + 9 == rBl) AB1 = __halves2half2(__low2half(AB1), oneh);
            }

            uint32_t a[4];
            a[0] = h2bits(AA0);
            a[1] = h2bits(AB0);
            a[2] = h2bits(AA1);
            a[3] = h2bits(AB1);

#pragma unroll
            for (int p = 0; p < 4; p++) {
                uint32_t bb[4];
                ldsm_x4_t(bb, pvBase + ks * (16 * XSTRIDE * 2) + p * 32);
                mma16816(C[rg][2 * p],     a, bb[0], bb[1]);
                mma16816(C[rg][2 * p + 1], a, bb[2], bb[3]);
            }
        }
    }
}

// ================= k2: S-MMA + f16x2 sigmoid + PV-MMA =================
__global__ __launch_bounds__(128) void k2_aggregate(
    const float* __restrict__ temp_p,
    const float* __restrict__ theta_p)
{
    __shared__ __align__(16) __half sB[128 * XSTRIDE];
    __shared__ __align__(16) __half szh[128 * ZSTRIDE];
    __shared__ float stq[128];

    const int tid  = threadIdx.x;
    const int wid  = tid >> 5;
    const int lane = tid & 31;
    const int g = lane >> 2;
    const int t = lane & 3;

    const int rowBase = blockIdx.x * 128;
    const int jbase0  = blockIdx.y * JCHUNK;

    const float L2E  = 1.4426950408889634f;
    const float temp = *temp_p;
    const float thL  = (*theta_p) * L2E;
    const float pS   = 2.f * temp * L2E;

    uint32_t aih[2][4], ail[2][4];
    float rc[2][2];
#pragma unroll
    for (int rg = 0; rg < 2; rg++) {
        int R  = rowBase + wid * 32 + rg * 16;
        int rA = R + g, rB = R + g + 8;
        aih[rg][0] = ld32g(g_zh + (size_t)rA * 16 + 2 * t);
        aih[rg][1] = ld32g(g_zh + (size_t)rB * 16 + 2 * t);
        aih[rg][2] = ld32g(g_zh + (size_t)rA * 16 + 2 * t + 8);
        aih[rg][3] = ld32g(g_zh + (size_t)rB * 16 + 2 * t + 8);
        ail[rg][0] = ld32g(g_zl + (size_t)rA * 16 + 2 * t);
        ail[rg][1] = ld32g(g_zl + (size_t)rB * 16 + 2 * t);
        ail[rg][2] = ld32g(g_zl + (size_t)rA * 16 + 2 * t + 8);
        ail[rg][3] = ld32g(g_zl + (size_t)rB * 16 + 2 * t + 8);
        rc[rg][0] = thL - g_tq[rA];
        rc[rg][1] = thL - g_tq[rB];
    }

    float C[2][8][4];
#pragma unroll
    for (int rg = 0; rg < 2; rg++)
#pragma unroll
        for (int nt = 0; nt < 8; nt++)
#pragma unroll
            for (int c = 0; c < 4; c++) C[rg][nt][c] = 0.f;

    const int lr = lane & 7;
    const int m4 = lane >> 3;
    const uint32_t pvBase = smem_u32(sB) +
        2 * (((m4 & 1) * 8 + lr) * XSTRIDE + (m4 >> 1) * 8);
    const int lz = lane & 15;
    const uint32_t zhBase = smem_u32(szh) +
        2 * ((lz & 7) * ZSTRIDE + ((lz >> 3) & 1) * 8);

    for (int tl = 0; tl < TILES; ++tl) {
        const int jbase = jbase0 + tl * 128;
        __syncthreads();
        {
            const uint4* xs = (const uint4*)(g_x16 + (size_t)(jbase + tid) * 64);
            uint4* xd = (uint4*)(sB + tid * XSTRIDE);
#pragma unroll
            for (int q = 0; q < 8; q++) xd[q] = xs[q];
            const uint4* hs = (const uint4*)(g_zh + (size_t)(jbase + tid) * 16);
            uint4* hd = (uint4*)(szh + tid * ZSTRIDE);
            hd[0] = hs[0]; hd[1] = hs[1];
            stq[tid] = g_tq[jbase + tid];
        }
        __syncthreads();

        if (jbase == rowBase)
            k2_tile<true >(pvBase, zhBase, stq, aih, ail, rc, pS, wid, g, t, C);
        else
            k2_tile<false>(pvBase, zhBase, stq, aih, ail, rc, pS, wid, g, t, C);
    }

#pragma unroll
    for (int rg = 0; rg < 2; rg++) {
        int rA = rowBase + wid * 32 + rg * 16 + g;
        float* b0 = g_part + ((size_t)blockIdx.y * N + rA) * 64;
        float* b1 = b0 + (size_t)8 * 64;
#pragma unroll
        for (int nt = 0; nt < 8; nt++) {
            int col = nt * 8 + 2 * t;
            *(float2*)(b0 + col) = make_float2(C[rg][nt][0], C[rg][nt][1]);
            *(float2*)(b1 + col) = make_float2(C[rg][nt][2], C[rg][nt][3]);
        }
    }
}

// ================= k3: parallel reduce -> normalize -> fc3 -> fc6 -> softmax =================
// 512 thr/block, 8 threads per row, 64 rows/block, grid 128.
__global__ __launch_bounds__(512) void k3_head(
    const float* __restrict__ w3, const float* __restrict__ b3,
    const float* __restrict__ w6, const float* __restrict__ b6,
    float* __restrict__ out)
{
    __shared__ float sw3[8 * 64];   // padded: cols 60..63 = 0
    __shared__ float sb3[8], sw6[10 * 8], sb6[10];
    int tid = threadIdx.x;
    if (tid < 512) {
        if (tid < 8 * 64) {
            int o = tid >> 6, k = tid & 63;
            sw3[tid] = (k < 60) ? w3[o * 60 + k] : 0.f;
        }
    }
    if (tid < 8)  sb3[tid] = b3[tid];
    else if (tid >= 32 && tid < 112) sw6[tid - 32] = w6[tid - 32];
    else if (tid >= 128 && tid < 138) sb6[tid - 128] = b6[tid - 128];
    __syncthreads();

    const int rloc = tid >> 3, sub = tid & 7;
    const int r = blockIdx.x * 64 + rloc;

    float acc[8];
#pragma unroll
    for (int k = 0; k < 8; k++) acc[k] = 0.f;
#pragma unroll
    for (int s = 0; s < SPLIT; s++) {
        const float4* p = (const float4*)(g_part + ((size_t)s * N + r) * 64 + sub * 8);
        float4 v0 = p[0], v1 = p[1];
        acc[0] += v0.x; acc[1] += v0.y; acc[2] += v0.z; acc[3] += v0.w;
        acc[4] += v1.x; acc[5] += v1.y; acc[6] += v1.z; acc[7] += v1.w;
    }

    // rowsum lives at col 60 -> sub 7, local idx 4
    const unsigned fullm = 0xffffffffu;
    float rs = __shfl_sync(fullm, acc[4], (tid & 31) | 7);
    float inv = 1.f / rs;
#pragma unroll
    for (int k = 0; k < 8; k++) acc[k] *= inv;

    // fc3 partials over this thread's 8 cols (padded w3 zeros kill cols 60..63)
    float p8[8];
#pragma unroll
    for (int o = 0; o < 8; o++) {
        const float* wrow = sw3 + o * 64 + sub * 8;
        float s = 0.f;
#pragma unroll
        for (int k = 0; k < 8; k++) s = fmaf(wrow[k], acc[k], s);
        p8[o] = s;
    }
#pragma unroll
    for (int d = 1; d < 8; d <<= 1)
#pragma unroll
        for (int o = 0; o < 8; o++) p8[o] += __shfl_xor_sync(fullm, p8[o], d);

    float tv[8];
#pragma unroll
    for (int o = 0; o < 8; o++) tv[o] = p8[o] + sb3[o];

    float u[10];
    float m = -1e30f;
#pragma unroll
    for (int c = 0; c < 10; c++) {
        float s = sb6[c];
#pragma unroll
        for (int o = 0; o < 8; o++) s = fmaf(sw6[c * 8 + o], tv[o], s);
        u[c] = s;
        m = fmaxf(m, s);
    }
    float denom = 0.f;
#pragma unroll
    for (int c = 0; c < 10; c++) { u[c] = __expf(u[c] - m); denom += u[c]; }
    float dinv = 1.f / denom;
    if (sub == 0) {
#pragma unroll
        for (int c = 0; c < 10; c++) out[(size_t)r * 10 + c] = u[c] * dinv;
    }
}

// ================= launch =================
extern "C" void kernel_launch(void* const* d_in, const int* in_sizes, int n_in,
                              void* d_out, int out_size)
{
    const float* x     = (const float*)d_in[0];
    const float* w1    = (const float*)d_in[1];
    const float* b1    = (const float*)d_in[2];
    const float* w2    = (const float*)d_in[3];
    const float* b2    = (const float*)d_in[4];
    const float* w3    = (const float*)d_in[5];
    const float* b3    = (const float*)d_in[6];
    const float* w6    = (const float*)d_in[7];
    const float* b6    = (const float*)d_in[8];
    const float* temp  = (const float*)d_in[9];
    const float* theta = (const float*)d_in[10];
    float* out = (float*)d_out;

    k1_embed<<<N / 32, 256>>>(x, w1, b1, w2, b2, temp);
    dim3 g2(N / 128, SPLIT);
    k2_aggregate<<<g2, 128>>>(temp, theta);
    k3_head<<<N / 64, 512>>>(w3, b3, w6, b6, out);
}